// round 14
// baseline (speedup 1.0000x reference)
#include <cuda_runtime.h>
#include <cuda_bf16.h>
#include <math.h>
#include <stdint.h>

#define N_NODES 50000
#define N_EDGES 600000
#define D 128
#define G 512
#define O 10
#define NBLK 196               // ceil(50000/256)
#define GEMM_TILES 391         // ceil(50000/128)

// Scratch (allocation-free rule: __device__ globals). Statics start zeroed;
// g_cnt is re-zeroed by the final k_agg and g_pool by k_head after reading,
// so every graph replay starts from identical state.
__device__ __align__(128) float g_A[N_NODES * D];   // hW buffer
__device__ __align__(128) float g_B[N_NODES * D];   // h buffer
__device__ __align__(128) float g_dis[N_NODES];
__device__ __align__(128) int   g_cnt[N_NODES];
__device__ __align__(128) int   g_rowptr[N_NODES];
__device__ __align__(128) int   g_cursor[N_NODES];
__device__ __align__(128) int2  g_epack[N_EDGES];   // {src, bits(nrm)}
__device__ __align__(128) int   g_bsum[NBLK];
__device__ __align__(128) float g_pool[G * D];
__device__ __align__(128) float g_pcnt[G];

// ---------------------------------------------------------------------------
// count in-degree over dst, 4 edges per thread (int4 loads feed the atomics)
// ---------------------------------------------------------------------------
__global__ void k_count(const int* __restrict__ ei) {
    int t = blockIdx.x * blockDim.x + threadIdx.x;
    if (t < N_EDGES / 4) {
        int4 d4 = ((const int4*)(ei + N_EDGES))[t];
        atomicAdd(&g_cnt[d4.x], 1);
        atomicAdd(&g_cnt[d4.y], 1);
        atomicAdd(&g_cnt[d4.z], 1);
        atomicAdd(&g_cnt[d4.w], 1);
    }
}

// phase 1: per-block inclusive scan of g_cnt -> local exclusive; also dis
__global__ void k_scan1() {
    __shared__ int s[256];
    int t = threadIdx.x;
    int i = blockIdx.x * 256 + t;
    int v = (i < N_NODES) ? g_cnt[i] : 0;
    if (i < N_NODES) g_dis[i] = rsqrtf((float)v + 1.0f);
    s[t] = v;
#pragma unroll
    for (int off = 1; off < 256; off <<= 1) {
        __syncthreads();
        int tmp = (t >= off) ? s[t - off] : 0;
        __syncthreads();
        s[t] += tmp;
    }
    if (i < N_NODES) g_rowptr[i] = s[t] - v;
    if (t == 255) g_bsum[blockIdx.x] = s[255];
}

// phase 2+3 fused: every block re-scans the 196 block sums (L2-hot) and
// applies its own exclusive offset.
__global__ void k_scan23() {
    __shared__ int s[256];
    int t = threadIdx.x;
    int v = (t < NBLK) ? g_bsum[t] : 0;
    s[t] = v;
#pragma unroll
    for (int off = 1; off < 256; off <<= 1) {
        __syncthreads();
        int tmp = (t >= off) ? s[t - off] : 0;
        __syncthreads();
        s[t] += tmp;
    }
    __syncthreads();
    int b = blockIdx.x;
    int excl = (b == 0) ? 0 : s[b - 1];
    int i = b * 256 + t;
    if (i < N_NODES) {
        int r = g_rowptr[i] + excl;
        g_rowptr[i] = r;
        g_cursor[i] = r;
    }
}

// fill CSR: packed {src, nrm}; 2 edges per thread (int2 loads)
__global__ void k_fill(const int* __restrict__ ei) {
    int t = blockIdx.x * blockDim.x + threadIdx.x;
    if (t >= N_EDGES / 2) return;
    int2 sv = ((const int2*)ei)[t];
    int2 dv = ((const int2*)(ei + N_EDGES))[t];
    int p0 = atomicAdd(&g_cursor[dv.x], 1);
    g_epack[p0] = make_int2(sv.x, __float_as_int(g_dis[sv.x] * g_dis[dv.x]));
    int p1 = atomicAdd(&g_cursor[dv.y], 1);
    g_epack[p1] = make_int2(sv.y, __float_as_int(g_dis[sv.y] * g_dis[dv.y]));
}

__global__ void k_pcnt(const int* __restrict__ batch) {
    int g = blockIdx.x * blockDim.x + threadIdx.x;
    if (g >= G) return;
    int lo = 0, hi = N_NODES;
    while (lo < hi) { int m = (lo + hi) >> 1; if (batch[m] < g) lo = m + 1; else hi = m; }
    int lb = lo;
    lo = 0; hi = N_NODES;
    while (lo < hi) { int m = (lo + hi) >> 1; if (batch[m] <= g) lo = m + 1; else hi = m; }
    g_pcnt[g] = (float)(lo - lb);
}

// ---------------------------------------------------------------------------
// tf32 split helpers (3xTF32 scheme: ~2^-21 effective precision)
// ---------------------------------------------------------------------------
__device__ __forceinline__ void split_tf32(float v, uint32_t& hi, uint32_t& lo) {
    uint32_t h;
    asm("cvt.rna.tf32.f32 %0, %1;" : "=r"(h) : "f"(v));
    float l = v - __uint_as_float(h);
    uint32_t l32;
    asm("cvt.rna.tf32.f32 %0, %1;" : "=r"(l32) : "f"(l));
    hi = h; lo = l32;
}

__device__ __forceinline__ void mma_tf32(float* c, const uint32_t* a, const uint32_t* b) {
    asm volatile(
        "mma.sync.aligned.m16n8k8.row.col.f32.tf32.tf32.f32 "
        "{%0,%1,%2,%3}, {%4,%5,%6,%7}, {%8,%9}, {%0,%1,%2,%3};"
        : "+f"(c[0]), "+f"(c[1]), "+f"(c[2]), "+f"(c[3])
        : "r"(a[0]), "r"(a[1]), "r"(a[2]), "r"(a[3]), "r"(b[0]), "r"(b[1]));
}

// ---------------------------------------------------------------------------
// GEMM via mma.sync tf32 (3xTF32) with register-prefetch software pipeline:
// loads for phase p+1 are issued before phase p's MMA loop, hiding the
// global-load latency behind the MMA/LDS stream. Same smem (2 CTAs/SM).
// ---------------------------------------------------------------------------
#define A_STRIDE 36
#define B_STRIDE 136
#define SM_AHI 0
#define SM_ALO (128 * A_STRIDE)            // floats
#define SM_BHI (2 * 128 * A_STRIDE)
#define SM_BLO (2 * 128 * A_STRIDE + 32 * B_STRIDE)
#define SMEM_GEMM_FLOATS (2 * 128 * A_STRIDE + 2 * 32 * B_STRIDE)
#define SMEM_GEMM_BYTES (SMEM_GEMM_FLOATS * 4)

__global__ void __launch_bounds__(256, 2) k_gemm_tc(const float* __restrict__ Xin,
                                                    const float* __restrict__ W,
                                                    int use_x, int n) {
    extern __shared__ float sm[];
    const float* A = use_x ? Xin : (const float*)g_B;

    int tid = threadIdx.x;
    int wid = tid >> 5, lane = tid & 31;
    int warp_m = wid >> 2, warp_n = wid & 3;
    int lg = lane >> 2, lt = lane & 3;     // groupID, threadID_in_group
    int row0 = blockIdx.x * 128;

    // per-thread staging coordinates (constant across phases)
    int a_row[4], a_cq[4], b_kk[4], b_nq[4];
#pragma unroll
    for (int i = 0; i < 4; i++) {
        int idx = tid + i * 256;
        a_row[i] = idx >> 3; a_cq[i] = idx & 7;
        b_kk[i] = idx >> 5;  b_nq[i] = idx & 31;
    }

    float acc[4][4][4];
#pragma unroll
    for (int mt = 0; mt < 4; mt++)
#pragma unroll
        for (int nt = 0; nt < 4; nt++)
#pragma unroll
            for (int q = 0; q < 4; q++) acc[mt][nt][q] = 0.0f;

    float4 ra[4], rb[4];
    // prologue: load phase 0
#pragma unroll
    for (int i = 0; i < 4; i++) {
        int gr = row0 + a_row[i];
        ra[i] = make_float4(0.f, 0.f, 0.f, 0.f);
        if (gr < n) ra[i] = *(const float4*)(A + (size_t)gr * D + a_cq[i] * 4);
        rb[i] = *(const float4*)(W + (size_t)b_kk[i] * D + b_nq[i] * 4);
    }

    for (int p = 0; p < 4; p++) {
        // store staged regs -> smem (split hi/lo at store time)
#pragma unroll
        for (int i = 0; i < 4; i++) {
            uint4 hi, lo;
            split_tf32(ra[i].x, hi.x, lo.x); split_tf32(ra[i].y, hi.y, lo.y);
            split_tf32(ra[i].z, hi.z, lo.z); split_tf32(ra[i].w, hi.w, lo.w);
            *(uint4*)&sm[SM_AHI + a_row[i] * A_STRIDE + a_cq[i] * 4] = hi;
            *(uint4*)&sm[SM_ALO + a_row[i] * A_STRIDE + a_cq[i] * 4] = lo;
            split_tf32(rb[i].x, hi.x, lo.x); split_tf32(rb[i].y, hi.y, lo.y);
            split_tf32(rb[i].z, hi.z, lo.z); split_tf32(rb[i].w, hi.w, lo.w);
            *(uint4*)&sm[SM_BHI + b_kk[i] * B_STRIDE + b_nq[i] * 4] = hi;
            *(uint4*)&sm[SM_BLO + b_kk[i] * B_STRIDE + b_nq[i] * 4] = lo;
        }
        __syncthreads();

        // prefetch phase p+1 into regs — latency hidden behind the MMA loop
        if (p < 3) {
            int k0n = (p + 1) * 32;
#pragma unroll
            for (int i = 0; i < 4; i++) {
                int gr = row0 + a_row[i];
                ra[i] = make_float4(0.f, 0.f, 0.f, 0.f);
                if (gr < n)
                    ra[i] = *(const float4*)(A + (size_t)gr * D + k0n + a_cq[i] * 4);
                rb[i] = *(const float4*)(W + (size_t)(k0n + b_kk[i]) * D + b_nq[i] * 4);
            }
        }

#pragma unroll
        for (int kk = 0; kk < 4; kk++) {
            int kb = kk * 8;
            uint32_t bhi[4][2], blo[4][2];
#pragma unroll
            for (int nt = 0; nt < 4; nt++) {
                int col = warp_n * 32 + nt * 8 + lg;
                bhi[nt][0] = __float_as_uint(sm[SM_BHI + (kb + lt) * B_STRIDE + col]);
                bhi[nt][1] = __float_as_uint(sm[SM_BHI + (kb + lt + 4) * B_STRIDE + col]);
                blo[nt][0] = __float_as_uint(sm[SM_BLO + (kb + lt) * B_STRIDE + col]);
                blo[nt][1] = __float_as_uint(sm[SM_BLO + (kb + lt + 4) * B_STRIDE + col]);
            }
#pragma unroll
            for (int mt = 0; mt < 4; mt++) {
                int rbase = warp_m * 64 + mt * 16;
                uint32_t ahi[4], alo[4];
                ahi[0] = __float_as_uint(sm[SM_AHI + (rbase + lg) * A_STRIDE + kb + lt]);
                ahi[1] = __float_as_uint(sm[SM_AHI + (rbase + lg + 8) * A_STRIDE + kb + lt]);
                ahi[2] = __float_as_uint(sm[SM_AHI + (rbase + lg) * A_STRIDE + kb + lt + 4]);
                ahi[3] = __float_as_uint(sm[SM_AHI + (rbase + lg + 8) * A_STRIDE + kb + lt + 4]);
                alo[0] = __float_as_uint(sm[SM_ALO + (rbase + lg) * A_STRIDE + kb + lt]);
                alo[1] = __float_as_uint(sm[SM_ALO + (rbase + lg + 8) * A_STRIDE + kb + lt]);
                alo[2] = __float_as_uint(sm[SM_ALO + (rbase + lg) * A_STRIDE + kb + lt + 4]);
                alo[3] = __float_as_uint(sm[SM_ALO + (rbase + lg + 8) * A_STRIDE + kb + lt + 4]);
#pragma unroll
                for (int nt = 0; nt < 4; nt++) {
                    mma_tf32(acc[mt][nt], ahi, bhi[nt]);   // hi*hi
                    mma_tf32(acc[mt][nt], alo, bhi[nt]);   // lo*hi
                    mma_tf32(acc[mt][nt], ahi, blo[nt]);   // hi*lo
                }
            }
        }
        __syncthreads();
    }

    // epilogue: write to g_A
#pragma unroll
    for (int mt = 0; mt < 4; mt++) {
        int r0 = row0 + warp_m * 64 + mt * 16 + lg;
#pragma unroll
        for (int nt = 0; nt < 4; nt++) {
            int col = warp_n * 32 + nt * 8 + 2 * lt;
            if (r0 < n)
                *(float2*)(g_A + (size_t)r0 * D + col) =
                    make_float2(acc[mt][nt][0], acc[mt][nt][1]);
            if (r0 + 8 < n)
                *(float2*)(g_A + (size_t)(r0 + 8) * D + col) =
                    make_float2(acc[mt][nt][2], acc[mt][nt][3]);
        }
    }
}

// ---------------------------------------------------------------------------
// fused aggregate: warp per node. Last layer (doPool) also zeroes g_cnt.
// ---------------------------------------------------------------------------
__global__ void k_agg(const float* __restrict__ bias,
                      const int* __restrict__ batch, int doPool) {
    int gt = blockIdx.x * blockDim.x + threadIdx.x;
    int w = gt >> 5;
    if (w >= N_NODES) return;
    int lane = gt & 31;

    float dv = g_dis[w];
    float sn = dv * dv;
    float4 h = ((const float4*)(g_A + (size_t)w * D))[lane];
    float4 acc = make_float4(sn * h.x, sn * h.y, sn * h.z, sn * h.w);

    int beg = g_rowptr[w];
    int end = beg + g_cnt[w];
    for (int k = beg; k < end; k++) {
        int2 p = g_epack[k];
        float nr = __int_as_float(p.y);
        float4 v = ((const float4*)(g_A + (size_t)p.x * D))[lane];
        acc.x += nr * v.x; acc.y += nr * v.y;
        acc.z += nr * v.z; acc.w += nr * v.w;
    }

    float4 bb = ((const float4*)bias)[lane];
    acc.x = fmaxf(acc.x + bb.x, 0.f);
    acc.y = fmaxf(acc.y + bb.y, 0.f);
    acc.z = fmaxf(acc.z + bb.z, 0.f);
    acc.w = fmaxf(acc.w + bb.w, 0.f);
    ((float4*)(g_B + (size_t)w * D))[lane] = acc;

    if (doPool) {
        float* pp = g_pool + (size_t)batch[w] * D + lane * 4;
        asm volatile("red.global.add.v4.f32 [%0], {%1,%2,%3,%4};"
                     :: "l"(pp), "f"(acc.x), "f"(acc.y), "f"(acc.z), "f"(acc.w)
                     : "memory");
        if (lane == 0) g_cnt[w] = 0;   // restore zeroed invariant
    }
}

// ---------------------------------------------------------------------------
// head: pooled mean -> linear(128->10) -> log_softmax. One warp per graph.
// Zeroes its g_pool row after reading (invariant for next replay).
// ---------------------------------------------------------------------------
__global__ void k_head(const float* __restrict__ Wf, const float* __restrict__ bf,
                       float* __restrict__ out) {
    int g = blockIdx.x;
    int lane = threadIdx.x;
    float inv = 1.0f / fmaxf(g_pcnt[g], 1.0f);
    float logit = -INFINITY;
    if (lane < O) {
        float s = bf[lane];
        const float* pr = g_pool + (size_t)g * D;
#pragma unroll 8
        for (int k = 0; k < D; k++)
            s += pr[k] * inv * Wf[k * O + lane];
        logit = s;
    }
    float m = logit;
#pragma unroll
    for (int o = 16; o; o >>= 1) m = fmaxf(m, __shfl_xor_sync(0xffffffffu, m, o));
    float e = (lane < O) ? expf(logit - m) : 0.0f;
    float se = e;
#pragma unroll
    for (int o = 16; o; o >>= 1) se += __shfl_xor_sync(0xffffffffu, se, o);
    if (lane < O) out[g * O + lane] = logit - m - logf(se);

    __syncwarp();
    ((float4*)(g_pool + (size_t)g * D))[lane] = make_float4(0.f, 0.f, 0.f, 0.f);
}

// ---------------------------------------------------------------------------
extern "C" void kernel_launch(void* const* d_in, const int* in_sizes, int n_in,
                              void* d_out, int out_size) {
    const float* x     = (const float*)d_in[0];
    const int*   ei    = (const int*)d_in[1];
    const int*   batch = (const int*)d_in[2];
    const float* W0 = (const float*)d_in[3];
    const float* b0 = (const float*)d_in[4];
    const float* W1 = (const float*)d_in[5];
    const float* b1 = (const float*)d_in[6];
    const float* W2 = (const float*)d_in[7];
    const float* b2 = (const float*)d_in[8];
    const float* Wf = (const float*)d_in[9];
    const float* bf = (const float*)d_in[10];
    float* out = (float*)d_out;

    cudaFuncSetAttribute(k_gemm_tc, cudaFuncAttributeMaxDynamicSharedMemorySize,
                         SMEM_GEMM_BYTES);

    // Side stream + events for fork/join inside the captured graph.
    static cudaStream_t s2 = nullptr;
    static cudaEvent_t e_fork = nullptr, e_join = nullptr;
    if (!s2) {
        cudaStreamCreateWithFlags(&s2, cudaStreamNonBlocking);
        cudaEventCreateWithFlags(&e_fork, cudaEventDisableTiming);
        cudaEventCreateWithFlags(&e_join, cudaEventDisableTiming);
    }

    // Fork: CSR build chain on s2, concurrent with layer-0 GEMM on main.
    cudaEventRecord(e_fork, 0);
    cudaStreamWaitEvent(s2, e_fork, 0);

    k_count<<<(N_EDGES / 4 + 255) / 256, 256, 0, s2>>>(ei);
    k_scan1<<<NBLK, 256, 0, s2>>>();
    k_scan23<<<NBLK, 256, 0, s2>>>();
    k_fill<<<(N_EDGES / 2 + 255) / 256, 256, 0, s2>>>(ei);
    cudaEventRecord(e_join, s2);

    // Layer-0 GEMM depends only on x/W0 — concurrent with CSR build.
    k_gemm_tc<<<GEMM_TILES, 256, SMEM_GEMM_BYTES>>>(x, W0, 1, N_NODES);
    // pcnt needs only batch; feeds only k_head.
    k_pcnt<<<(G + 255) / 256, 256>>>(batch);

    // Join: everything after needs the CSR.
    cudaStreamWaitEvent(0, e_join, 0);

    const float* Ws[3] = {W0, W1, W2};
    const float* bs[3] = {b0, b1, b2};
    int agg_blocks = (N_NODES * 32 + 255) / 256;

    for (int l = 0; l < 3; l++) {
        if (l > 0)
            k_gemm_tc<<<GEMM_TILES, 256, SMEM_GEMM_BYTES>>>(x, Ws[l], 0, N_NODES);
        k_agg<<<agg_blocks, 256>>>(bs[l], batch, l == 2 ? 1 : 0);
    }

    k_head<<<G, 32>>>(Wf, bf, out);   // zeroes g_pool after reading
}

// round 15
// speedup vs baseline: 1.0938x; 1.0938x over previous
#include <cuda_runtime.h>
#include <cuda_bf16.h>
#include <math.h>
#include <stdint.h>

#define N_NODES 50000
#define N_EDGES 600000
#define D 128
#define G 512
#define O 10
#define NBLK 196               // ceil(50000/256)
#define GEMM_TILES 391         // ceil(50000/128)

// Scratch (allocation-free rule: __device__ globals)
__device__ __align__(128) float g_A[N_NODES * D];   // hW buffer
__device__ __align__(128) float g_B[N_NODES * D];   // h buffer
__device__ __align__(128) float g_dis[N_NODES];
__device__ __align__(128) int   g_cnt[N_NODES];
__device__ __align__(128) int   g_rowptr[N_NODES];
__device__ __align__(128) int   g_cursor[N_NODES];
__device__ __align__(128) int   g_csrc[N_EDGES];
__device__ __align__(128) float g_cnrm[N_EDGES];
__device__ __align__(128) int   g_bsum[NBLK];
__device__ __align__(128) int   g_boff[NBLK];
__device__ __align__(128) float g_pool[G * D];
__device__ __align__(128) float g_pcnt[G];

// ---------------------------------------------------------------------------
// prep: zero cnt + pool
// ---------------------------------------------------------------------------
__global__ void k_prep() {
    int i = blockIdx.x * blockDim.x + threadIdx.x;
    if (i < N_NODES) g_cnt[i] = 0;
    if (i < G * D)   g_pool[i] = 0.0f;
}

__global__ void k_count(const int* __restrict__ ei) {
    int e = blockIdx.x * blockDim.x + threadIdx.x;
    if (e < N_EDGES) atomicAdd(&g_cnt[ei[N_EDGES + e]], 1);
}

// 3-phase exclusive scan of g_cnt -> g_rowptr ; also compute dis
__global__ void k_scan1() {
    __shared__ int s[256];
    int t = threadIdx.x;
    int i = blockIdx.x * 256 + t;
    int v = (i < N_NODES) ? g_cnt[i] : 0;
    if (i < N_NODES) g_dis[i] = rsqrtf((float)v + 1.0f);
    s[t] = v;
#pragma unroll
    for (int off = 1; off < 256; off <<= 1) {
        __syncthreads();
        int tmp = (t >= off) ? s[t - off] : 0;
        __syncthreads();
        s[t] += tmp;
    }
    if (i < N_NODES) g_rowptr[i] = s[t] - v;
    if (t == 255) g_bsum[blockIdx.x] = s[255];
}

__global__ void k_scan2() {
    __shared__ int s[256];
    int t = threadIdx.x;
    int v = (t < NBLK) ? g_bsum[t] : 0;
    s[t] = v;
#pragma unroll
    for (int off = 1; off < 256; off <<= 1) {
        __syncthreads();
        int tmp = (t >= off) ? s[t - off] : 0;
        __syncthreads();
        s[t] += tmp;
    }
    if (t < NBLK) g_boff[t] = s[t] - v;
}

__global__ void k_scan3() {
    int i = blockIdx.x * 256 + threadIdx.x;
    if (i < N_NODES) {
        int r = g_rowptr[i] + g_boff[blockIdx.x];
        g_rowptr[i] = r;
        g_cursor[i] = r;
    }
}

__global__ void k_fill(const int* __restrict__ ei) {
    int e = blockIdx.x * blockDim.x + threadIdx.x;
    if (e >= N_EDGES) return;
    int s = ei[e];
    int d = ei[N_EDGES + e];
    int pos = atomicAdd(&g_cursor[d], 1);
    g_csrc[pos] = s;
    g_cnrm[pos] = g_dis[s] * g_dis[d];
}

__global__ void k_pcnt(const int* __restrict__ batch) {
    int g = blockIdx.x * blockDim.x + threadIdx.x;
    if (g >= G) return;
    int lo = 0, hi = N_NODES;
    while (lo < hi) { int m = (lo + hi) >> 1; if (batch[m] < g) lo = m + 1; else hi = m; }
    int lb = lo;
    lo = 0; hi = N_NODES;
    while (lo < hi) { int m = (lo + hi) >> 1; if (batch[m] <= g) lo = m + 1; else hi = m; }
    g_pcnt[g] = (float)(lo - lb);
}

// ---------------------------------------------------------------------------
// tf32 split helpers (3xTF32 scheme: ~2^-21 effective precision)
// ---------------------------------------------------------------------------
__device__ __forceinline__ void split_tf32(float v, uint32_t& hi, uint32_t& lo) {
    uint32_t h;
    asm("cvt.rna.tf32.f32 %0, %1;" : "=r"(h) : "f"(v));
    float l = v - __uint_as_float(h);
    uint32_t l32;
    asm("cvt.rna.tf32.f32 %0, %1;" : "=r"(l32) : "f"(l));
    hi = h; lo = l32;
}

__device__ __forceinline__ void mma_tf32(float* c, const uint32_t* a, const uint32_t* b) {
    asm volatile(
        "mma.sync.aligned.m16n8k8.row.col.f32.tf32.tf32.f32 "
        "{%0,%1,%2,%3}, {%4,%5,%6,%7}, {%8,%9}, {%0,%1,%2,%3};"
        : "+f"(c[0]), "+f"(c[1]), "+f"(c[2]), "+f"(c[3])
        : "r"(a[0]), "r"(a[1]), "r"(a[2]), "r"(a[3]), "r"(b[0]), "r"(b[1]));
}

// ---------------------------------------------------------------------------
// GEMM via mma.sync tf32 (3xTF32): g_A = in @ W  (in = x if use_x else g_B)
// BM=128, BN=128, BK=32 x 4 phases. 256 threads = 8 warps (2m x 4n),
// warp tile 64x32. (Measured-best round-9 configuration, byte-identical.)
// ---------------------------------------------------------------------------
#define A_STRIDE 36
#define B_STRIDE 136
#define SM_AHI 0
#define SM_ALO (128 * A_STRIDE)            // floats
#define SM_BHI (2 * 128 * A_STRIDE)
#define SM_BLO (2 * 128 * A_STRIDE + 32 * B_STRIDE)
#define SMEM_GEMM_FLOATS (2 * 128 * A_STRIDE + 2 * 32 * B_STRIDE)
#define SMEM_GEMM_BYTES (SMEM_GEMM_FLOATS * 4)

__global__ void __launch_bounds__(256, 2) k_gemm_tc(const float* __restrict__ Xin,
                                                    const float* __restrict__ W,
                                                    int use_x, int n) {
    extern __shared__ float sm[];
    const float* A = use_x ? Xin : (const float*)g_B;

    int tid = threadIdx.x;
    int wid = tid >> 5, lane = tid & 31;
    int warp_m = wid >> 2, warp_n = wid & 3;
    int lg = lane >> 2, lt = lane & 3;     // groupID, threadID_in_group
    int row0 = blockIdx.x * 128;

    float acc[4][4][4];
#pragma unroll
    for (int mt = 0; mt < 4; mt++)
#pragma unroll
        for (int nt = 0; nt < 4; nt++)
#pragma unroll
            for (int q = 0; q < 4; q++) acc[mt][nt][q] = 0.0f;

    for (int p = 0; p < 4; p++) {
        int k0 = p * 32;
        // stage A chunk: 128 rows x 32 cols = 1024 float4s, 4 per thread
#pragma unroll
        for (int i = 0; i < 4; i++) {
            int idx = tid + i * 256;
            int row = idx >> 3, cq = idx & 7;
            int gr = row0 + row;
            float4 v = make_float4(0.f, 0.f, 0.f, 0.f);
            if (gr < n) v = *(const float4*)(A + (size_t)gr * D + k0 + cq * 4);
            uint4 hi, lo;
            split_tf32(v.x, hi.x, lo.x); split_tf32(v.y, hi.y, lo.y);
            split_tf32(v.z, hi.z, lo.z); split_tf32(v.w, hi.w, lo.w);
            *(uint4*)&sm[SM_AHI + row * A_STRIDE + cq * 4] = hi;
            *(uint4*)&sm[SM_ALO + row * A_STRIDE + cq * 4] = lo;
        }
        // stage B chunk: 32 k-rows x 128 cols = 1024 float4s, 4 per thread
#pragma unroll
        for (int i = 0; i < 4; i++) {
            int idx = tid + i * 256;
            int kk = idx >> 5, nq = idx & 31;
            float4 v = *(const float4*)(W + (size_t)(k0 + kk) * D + nq * 4);
            uint4 hi, lo;
            split_tf32(v.x, hi.x, lo.x); split_tf32(v.y, hi.y, lo.y);
            split_tf32(v.z, hi.z, lo.z); split_tf32(v.w, hi.w, lo.w);
            *(uint4*)&sm[SM_BHI + kk * B_STRIDE + nq * 4] = hi;
            *(uint4*)&sm[SM_BLO + kk * B_STRIDE + nq * 4] = lo;
        }
        __syncthreads();

#pragma unroll
        for (int kk = 0; kk < 4; kk++) {
            int kb = kk * 8;
            uint32_t bhi[4][2], blo[4][2];
#pragma unroll
            for (int nt = 0; nt < 4; nt++) {
                int col = warp_n * 32 + nt * 8 + lg;
                bhi[nt][0] = __float_as_uint(sm[SM_BHI + (kb + lt) * B_STRIDE + col]);
                bhi[nt][1] = __float_as_uint(sm[SM_BHI + (kb + lt + 4) * B_STRIDE + col]);
                blo[nt][0] = __float_as_uint(sm[SM_BLO + (kb + lt) * B_STRIDE + col]);
                blo[nt][1] = __float_as_uint(sm[SM_BLO + (kb + lt + 4) * B_STRIDE + col]);
            }
#pragma unroll
            for (int mt = 0; mt < 4; mt++) {
                int rbase = warp_m * 64 + mt * 16;
                uint32_t ahi[4], alo[4];
                ahi[0] = __float_as_uint(sm[SM_AHI + (rbase + lg) * A_STRIDE + kb + lt]);
                ahi[1] = __float_as_uint(sm[SM_AHI + (rbase + lg + 8) * A_STRIDE + kb + lt]);
                ahi[2] = __float_as_uint(sm[SM_AHI + (rbase + lg) * A_STRIDE + kb + lt + 4]);
                ahi[3] = __float_as_uint(sm[SM_AHI + (rbase + lg + 8) * A_STRIDE + kb + lt + 4]);
                alo[0] = __float_as_uint(sm[SM_ALO + (rbase + lg) * A_STRIDE + kb + lt]);
                alo[1] = __float_as_uint(sm[SM_ALO + (rbase + lg + 8) * A_STRIDE + kb + lt]);
                alo[2] = __float_as_uint(sm[SM_ALO + (rbase + lg) * A_STRIDE + kb + lt + 4]);
                alo[3] = __float_as_uint(sm[SM_ALO + (rbase + lg + 8) * A_STRIDE + kb + lt + 4]);
#pragma unroll
                for (int nt = 0; nt < 4; nt++) {
                    mma_tf32(acc[mt][nt], ahi, bhi[nt]);   // hi*hi
                    mma_tf32(acc[mt][nt], alo, bhi[nt]);   // lo*hi
                    mma_tf32(acc[mt][nt], ahi, blo[nt]);   // hi*lo
                }
            }
        }
        __syncthreads();
    }

    // epilogue: write to g_A
#pragma unroll
    for (int mt = 0; mt < 4; mt++) {
        int r0 = row0 + warp_m * 64 + mt * 16 + lg;
#pragma unroll
        for (int nt = 0; nt < 4; nt++) {
            int col = warp_n * 32 + nt * 8 + 2 * lt;
            if (r0 < n)
                *(float2*)(g_A + (size_t)r0 * D + col) =
                    make_float2(acc[mt][nt][0], acc[mt][nt][1]);
            if (r0 + 8 < n)
                *(float2*)(g_A + (size_t)(r0 + 8) * D + col) =
                    make_float2(acc[mt][nt][2], acc[mt][nt][3]);
        }
    }
}

// ---------------------------------------------------------------------------
// fused aggregate: warp per node (round-9 exact version — measured best).
// ---------------------------------------------------------------------------
__global__ void k_agg(const float* __restrict__ bias,
                      const int* __restrict__ batch, int doPool) {
    int gt = blockIdx.x * blockDim.x + threadIdx.x;
    int w = gt >> 5;
    if (w >= N_NODES) return;
    int lane = gt & 31;

    float dv = g_dis[w];
    float sn = dv * dv;
    float4 h = ((const float4*)(g_A + (size_t)w * D))[lane];
    float4 acc = make_float4(sn * h.x, sn * h.y, sn * h.z, sn * h.w);

    int beg = g_rowptr[w];
    int end = beg + g_cnt[w];
    for (int k = beg; k < end; k++) {
        int s = g_csrc[k];
        float nr = g_cnrm[k];
        float4 v = ((const float4*)(g_A + (size_t)s * D))[lane];
        acc.x += nr * v.x; acc.y += nr * v.y;
        acc.z += nr * v.z; acc.w += nr * v.w;
    }

    float4 bb = ((const float4*)bias)[lane];
    acc.x = fmaxf(acc.x + bb.x, 0.f);
    acc.y = fmaxf(acc.y + bb.y, 0.f);
    acc.z = fmaxf(acc.z + bb.z, 0.f);
    acc.w = fmaxf(acc.w + bb.w, 0.f);
    ((float4*)(g_B + (size_t)w * D))[lane] = acc;

    if (doPool) {
        float* pp = g_pool + (size_t)batch[w] * D + lane * 4;
        asm volatile("red.global.add.v4.f32 [%0], {%1,%2,%3,%4};"
                     :: "l"(pp), "f"(acc.x), "f"(acc.y), "f"(acc.z), "f"(acc.w)
                     : "memory");
    }
}

// ---------------------------------------------------------------------------
// head: pooled mean -> linear(128->10) -> log_softmax. One warp per graph.
// ---------------------------------------------------------------------------
__global__ void k_head(const float* __restrict__ Wf, const float* __restrict__ bf,
                       float* __restrict__ out) {
    int g = blockIdx.x;
    int lane = threadIdx.x;
    float inv = 1.0f / fmaxf(g_pcnt[g], 1.0f);
    float logit = -INFINITY;
    if (lane < O) {
        float s = bf[lane];
        const float* pr = g_pool + (size_t)g * D;
#pragma unroll 8
        for (int k = 0; k < D; k++)
            s += pr[k] * inv * Wf[k * O + lane];
        logit = s;
    }
    float m = logit;
#pragma unroll
    for (int o = 16; o; o >>= 1) m = fmaxf(m, __shfl_xor_sync(0xffffffffu, m, o));
    float e = (lane < O) ? expf(logit - m) : 0.0f;
    float se = e;
#pragma unroll
    for (int o = 16; o; o >>= 1) se += __shfl_xor_sync(0xffffffffu, se, o);
    if (lane < O) out[g * O + lane] = logit - m - logf(se);
}

// ---------------------------------------------------------------------------
extern "C" void kernel_launch(void* const* d_in, const int* in_sizes, int n_in,
                              void* d_out, int out_size) {
    const float* x     = (const float*)d_in[0];
    const int*   ei    = (const int*)d_in[1];
    const int*   batch = (const int*)d_in[2];
    const float* W0 = (const float*)d_in[3];
    const float* b0 = (const float*)d_in[4];
    const float* W1 = (const float*)d_in[5];
    const float* b1 = (const float*)d_in[6];
    const float* W2 = (const float*)d_in[7];
    const float* b2 = (const float*)d_in[8];
    const float* Wf = (const float*)d_in[9];
    const float* bf = (const float*)d_in[10];
    float* out = (float*)d_out;

    cudaFuncSetAttribute(k_gemm_tc, cudaFuncAttributeMaxDynamicSharedMemorySize,
                         SMEM_GEMM_BYTES);

    // Side stream + events for fork/join inside the captured graph.
    static cudaStream_t s2 = nullptr;
    static cudaEvent_t e_fork = nullptr, e_join = nullptr;
    if (!s2) {
        cudaStreamCreateWithFlags(&s2, cudaStreamNonBlocking);
        cudaEventCreateWithFlags(&e_fork, cudaEventDisableTiming);
        cudaEventCreateWithFlags(&e_join, cudaEventDisableTiming);
    }

    // Fork: CSR build chain on s2, concurrent with layer-0 GEMM on main stream.
    cudaEventRecord(e_fork, 0);
    cudaStreamWaitEvent(s2, e_fork, 0);

    k_prep<<<(G * D + 255) / 256, 256, 0, s2>>>();
    k_count<<<(N_EDGES + 255) / 256, 256, 0, s2>>>(ei);
    k_scan1<<<NBLK, 256, 0, s2>>>();
    k_scan2<<<1, 256, 0, s2>>>();
    k_scan3<<<NBLK, 256, 0, s2>>>();
    k_fill<<<(N_EDGES + 255) / 256, 256, 0, s2>>>(ei);
    cudaEventRecord(e_join, s2);

    // Layer-0 GEMM depends only on x/W0 — concurrent with CSR build.
    k_gemm_tc<<<GEMM_TILES, 256, SMEM_GEMM_BYTES>>>(x, W0, 1, N_NODES);
    // pcnt needs only batch; feeds only k_head. Runs on main after gemm0,
    // filling the idle gap before the join instead of extending the chain.
    k_pcnt<<<(G + 255) / 256, 256>>>(batch);

    // Join: everything after needs the CSR.
    cudaStreamWaitEvent(0, e_join, 0);

    const float* Ws[3] = {W0, W1, W2};
    const float* bs[3] = {b0, b1, b2};
    int agg_blocks = (N_NODES * 32 + 255) / 256;

    for (int l = 0; l < 3; l++) {
        if (l > 0)
            k_gemm_tc<<<GEMM_TILES, 256, SMEM_GEMM_BYTES>>>(x, Ws[l], 0, N_NODES);
        k_agg<<<agg_blocks, 256>>>(bs[l], batch, l == 2 ? 1 : 0);
    }

    k_head<<<G, 32>>>(Wf, bf, out);
}

// round 16
// speedup vs baseline: 1.1759x; 1.0750x over previous
#include <cuda_runtime.h>
#include <cuda_bf16.h>
#include <cuda_fp16.h>
#include <math.h>
#include <stdint.h>

#define N_NODES 50000
#define N_EDGES 600000
#define D 128
#define G 512
#define O 10
#define NBLK 196               // ceil(50000/256)
#define GEMM_TILES 391         // ceil(50000/128)

// Scratch (allocation-free rule: __device__ globals)
__device__ __align__(128) __half g_Ah[N_NODES * D]; // hW buffer (fp16 — gather)
__device__ __align__(128) float g_B[N_NODES * D];   // h buffer (fp32 — GEMM in)
__device__ __align__(128) float g_dis[N_NODES];
__device__ __align__(128) int   g_cnt[N_NODES];
__device__ __align__(128) int   g_rowptr[N_NODES];
__device__ __align__(128) int   g_cursor[N_NODES];
__device__ __align__(128) int   g_csrc[N_EDGES];
__device__ __align__(128) float g_cnrm[N_EDGES];
__device__ __align__(128) int   g_bsum[NBLK];
__device__ __align__(128) int   g_boff[NBLK];
__device__ __align__(128) float g_pool[G * D];
__device__ __align__(128) float g_pcnt[G];

// ---------------------------------------------------------------------------
// prep: zero cnt + pool
// ---------------------------------------------------------------------------
__global__ void k_prep() {
    int i = blockIdx.x * blockDim.x + threadIdx.x;
    if (i < N_NODES) g_cnt[i] = 0;
    if (i < G * D)   g_pool[i] = 0.0f;
}

__global__ void k_count(const int* __restrict__ ei) {
    int e = blockIdx.x * blockDim.x + threadIdx.x;
    if (e < N_EDGES) atomicAdd(&g_cnt[ei[N_EDGES + e]], 1);
}

// 3-phase exclusive scan of g_cnt -> g_rowptr ; also compute dis
__global__ void k_scan1() {
    __shared__ int s[256];
    int t = threadIdx.x;
    int i = blockIdx.x * 256 + t;
    int v = (i < N_NODES) ? g_cnt[i] : 0;
    if (i < N_NODES) g_dis[i] = rsqrtf((float)v + 1.0f);
    s[t] = v;
#pragma unroll
    for (int off = 1; off < 256; off <<= 1) {
        __syncthreads();
        int tmp = (t >= off) ? s[t - off] : 0;
        __syncthreads();
        s[t] += tmp;
    }
    if (i < N_NODES) g_rowptr[i] = s[t] - v;
    if (t == 255) g_bsum[blockIdx.x] = s[255];
}

__global__ void k_scan2() {
    __shared__ int s[256];
    int t = threadIdx.x;
    int v = (t < NBLK) ? g_bsum[t] : 0;
    s[t] = v;
#pragma unroll
    for (int off = 1; off < 256; off <<= 1) {
        __syncthreads();
        int tmp = (t >= off) ? s[t - off] : 0;
        __syncthreads();
        s[t] += tmp;
    }
    if (t < NBLK) g_boff[t] = s[t] - v;
}

__global__ void k_scan3() {
    int i = blockIdx.x * 256 + threadIdx.x;
    if (i < N_NODES) {
        int r = g_rowptr[i] + g_boff[blockIdx.x];
        g_rowptr[i] = r;
        g_cursor[i] = r;
    }
}

__global__ void k_fill(const int* __restrict__ ei) {
    int e = blockIdx.x * blockDim.x + threadIdx.x;
    if (e >= N_EDGES) return;
    int s = ei[e];
    int d = ei[N_EDGES + e];
    int pos = atomicAdd(&g_cursor[d], 1);
    g_csrc[pos] = s;
    g_cnrm[pos] = g_dis[s] * g_dis[d];
}

__global__ void k_pcnt(const int* __restrict__ batch) {
    int g = blockIdx.x * blockDim.x + threadIdx.x;
    if (g >= G) return;
    int lo = 0, hi = N_NODES;
    while (lo < hi) { int m = (lo + hi) >> 1; if (batch[m] < g) lo = m + 1; else hi = m; }
    int lb = lo;
    lo = 0; hi = N_NODES;
    while (lo < hi) { int m = (lo + hi) >> 1; if (batch[m] <= g) lo = m + 1; else hi = m; }
    g_pcnt[g] = (float)(lo - lb);
}

// ---------------------------------------------------------------------------
// tf32 split helpers (3xTF32 scheme: ~2^-21 effective precision)
// ---------------------------------------------------------------------------
__device__ __forceinline__ void split_tf32(float v, uint32_t& hi, uint32_t& lo) {
    uint32_t h;
    asm("cvt.rna.tf32.f32 %0, %1;" : "=r"(h) : "f"(v));
    float l = v - __uint_as_float(h);
    uint32_t l32;
    asm("cvt.rna.tf32.f32 %0, %1;" : "=r"(l32) : "f"(l));
    hi = h; lo = l32;
}

__device__ __forceinline__ void mma_tf32(float* c, const uint32_t* a, const uint32_t* b) {
    asm volatile(
        "mma.sync.aligned.m16n8k8.row.col.f32.tf32.tf32.f32 "
        "{%0,%1,%2,%3}, {%4,%5,%6,%7}, {%8,%9}, {%0,%1,%2,%3};"
        : "+f"(c[0]), "+f"(c[1]), "+f"(c[2]), "+f"(c[3])
        : "r"(a[0]), "r"(a[1]), "r"(a[2]), "r"(a[3]), "r"(b[0]), "r"(b[1]));
}

// ---------------------------------------------------------------------------
// GEMM via mma.sync tf32 (3xTF32): g_Ah = fp16(in @ W)  (in = x or g_B)
// BM=128, BN=128, BK=32 x 4 phases. 256 threads = 8 warps (2m x 4n),
// warp tile 64x32. Mainloop identical to measured-best; epilogue stores fp16.
// ---------------------------------------------------------------------------
#define A_STRIDE 36
#define B_STRIDE 136
#define SM_AHI 0
#define SM_ALO (128 * A_STRIDE)            // floats
#define SM_BHI (2 * 128 * A_STRIDE)
#define SM_BLO (2 * 128 * A_STRIDE + 32 * B_STRIDE)
#define SMEM_GEMM_FLOATS (2 * 128 * A_STRIDE + 2 * 32 * B_STRIDE)
#define SMEM_GEMM_BYTES (SMEM_GEMM_FLOATS * 4)

__global__ void __launch_bounds__(256, 2) k_gemm_tc(const float* __restrict__ Xin,
                                                    const float* __restrict__ W,
                                                    int use_x, int n) {
    extern __shared__ float sm[];
    const float* A = use_x ? Xin : (const float*)g_B;

    int tid = threadIdx.x;
    int wid = tid >> 5, lane = tid & 31;
    int warp_m = wid >> 2, warp_n = wid & 3;
    int lg = lane >> 2, lt = lane & 3;     // groupID, threadID_in_group
    int row0 = blockIdx.x * 128;

    float acc[4][4][4];
#pragma unroll
    for (int mt = 0; mt < 4; mt++)
#pragma unroll
        for (int nt = 0; nt < 4; nt++)
#pragma unroll
            for (int q = 0; q < 4; q++) acc[mt][nt][q] = 0.0f;

    for (int p = 0; p < 4; p++) {
        int k0 = p * 32;
        // stage A chunk: 128 rows x 32 cols = 1024 float4s, 4 per thread
#pragma unroll
        for (int i = 0; i < 4; i++) {
            int idx = tid + i * 256;
            int row = idx >> 3, cq = idx & 7;
            int gr = row0 + row;
            float4 v = make_float4(0.f, 0.f, 0.f, 0.f);
            if (gr < n) v = *(const float4*)(A + (size_t)gr * D + k0 + cq * 4);
            uint4 hi, lo;
            split_tf32(v.x, hi.x, lo.x); split_tf32(v.y, hi.y, lo.y);
            split_tf32(v.z, hi.z, lo.z); split_tf32(v.w, hi.w, lo.w);
            *(uint4*)&sm[SM_AHI + row * A_STRIDE + cq * 4] = hi;
            *(uint4*)&sm[SM_ALO + row * A_STRIDE + cq * 4] = lo;
        }
        // stage B chunk: 32 k-rows x 128 cols = 1024 float4s, 4 per thread
#pragma unroll
        for (int i = 0; i < 4; i++) {
            int idx = tid + i * 256;
            int kk = idx >> 5, nq = idx & 31;
            float4 v = *(const float4*)(W + (size_t)(k0 + kk) * D + nq * 4);
            uint4 hi, lo;
            split_tf32(v.x, hi.x, lo.x); split_tf32(v.y, hi.y, lo.y);
            split_tf32(v.z, hi.z, lo.z); split_tf32(v.w, hi.w, lo.w);
            *(uint4*)&sm[SM_BHI + kk * B_STRIDE + nq * 4] = hi;
            *(uint4*)&sm[SM_BLO + kk * B_STRIDE + nq * 4] = lo;
        }
        __syncthreads();

#pragma unroll
        for (int kk = 0; kk < 4; kk++) {
            int kb = kk * 8;
            uint32_t bhi[4][2], blo[4][2];
#pragma unroll
            for (int nt = 0; nt < 4; nt++) {
                int col = warp_n * 32 + nt * 8 + lg;
                bhi[nt][0] = __float_as_uint(sm[SM_BHI + (kb + lt) * B_STRIDE + col]);
                bhi[nt][1] = __float_as_uint(sm[SM_BHI + (kb + lt + 4) * B_STRIDE + col]);
                blo[nt][0] = __float_as_uint(sm[SM_BLO + (kb + lt) * B_STRIDE + col]);
                blo[nt][1] = __float_as_uint(sm[SM_BLO + (kb + lt + 4) * B_STRIDE + col]);
            }
#pragma unroll
            for (int mt = 0; mt < 4; mt++) {
                int rbase = warp_m * 64 + mt * 16;
                uint32_t ahi[4], alo[4];
                ahi[0] = __float_as_uint(sm[SM_AHI + (rbase + lg) * A_STRIDE + kb + lt]);
                ahi[1] = __float_as_uint(sm[SM_AHI + (rbase + lg + 8) * A_STRIDE + kb + lt]);
                ahi[2] = __float_as_uint(sm[SM_AHI + (rbase + lg) * A_STRIDE + kb + lt + 4]);
                ahi[3] = __float_as_uint(sm[SM_AHI + (rbase + lg + 8) * A_STRIDE + kb + lt + 4]);
                alo[0] = __float_as_uint(sm[SM_ALO + (rbase + lg) * A_STRIDE + kb + lt]);
                alo[1] = __float_as_uint(sm[SM_ALO + (rbase + lg + 8) * A_STRIDE + kb + lt]);
                alo[2] = __float_as_uint(sm[SM_ALO + (rbase + lg) * A_STRIDE + kb + lt + 4]);
                alo[3] = __float_as_uint(sm[SM_ALO + (rbase + lg + 8) * A_STRIDE + kb + lt + 4]);
#pragma unroll
                for (int nt = 0; nt < 4; nt++) {
                    mma_tf32(acc[mt][nt], ahi, bhi[nt]);   // hi*hi
                    mma_tf32(acc[mt][nt], alo, bhi[nt]);   // lo*hi
                    mma_tf32(acc[mt][nt], ahi, blo[nt]);   // hi*lo
                }
            }
        }
        __syncthreads();
    }

    // epilogue: write fp16 to g_Ah
#pragma unroll
    for (int mt = 0; mt < 4; mt++) {
        int r0 = row0 + warp_m * 64 + mt * 16 + lg;
#pragma unroll
        for (int nt = 0; nt < 4; nt++) {
            int col = warp_n * 32 + nt * 8 + 2 * lt;
            if (r0 < n)
                *(__half2*)(g_Ah + (size_t)r0 * D + col) =
                    __floats2half2_rn(acc[mt][nt][0], acc[mt][nt][1]);
            if (r0 + 8 < n)
                *(__half2*)(g_Ah + (size_t)(r0 + 8) * D + col) =
                    __floats2half2_rn(acc[mt][nt][2], acc[mt][nt][3]);
        }
    }
}

// ---------------------------------------------------------------------------
// fused aggregate: warp per node; gathers fp16 rows (half the L2 traffic),
// accumulates fp32. Lane handles dims [4*lane, 4*lane+4) via one 8B load.
// ---------------------------------------------------------------------------
__global__ void k_agg(const float* __restrict__ bias,
                      const int* __restrict__ batch, int doPool) {
    int gt = blockIdx.x * blockDim.x + threadIdx.x;
    int w = gt >> 5;
    if (w >= N_NODES) return;
    int lane = gt & 31;

    float dv = g_dis[w];
    float sn = dv * dv;

    uint2 rh = *(const uint2*)(g_Ah + (size_t)w * D + lane * 4);
    float2 h01 = __half22float2(*(const __half2*)&rh.x);
    float2 h23 = __half22float2(*(const __half2*)&rh.y);
    float4 acc = make_float4(sn * h01.x, sn * h01.y, sn * h23.x, sn * h23.y);

    int beg = g_rowptr[w];
    int end = beg + g_cnt[w];
    for (int k = beg; k < end; k++) {
        int s = g_csrc[k];
        float nr = g_cnrm[k];
        uint2 rv = *(const uint2*)(g_Ah + (size_t)s * D + lane * 4);
        float2 v01 = __half22float2(*(const __half2*)&rv.x);
        float2 v23 = __half22float2(*(const __half2*)&rv.y);
        acc.x += nr * v01.x; acc.y += nr * v01.y;
        acc.z += nr * v23.x; acc.w += nr * v23.y;
    }

    float4 bb = ((const float4*)bias)[lane];
    acc.x = fmaxf(acc.x + bb.x, 0.f);
    acc.y = fmaxf(acc.y + bb.y, 0.f);
    acc.z = fmaxf(acc.z + bb.z, 0.f);
    acc.w = fmaxf(acc.w + bb.w, 0.f);
    ((float4*)(g_B + (size_t)w * D))[lane] = acc;

    if (doPool) {
        float* pp = g_pool + (size_t)batch[w] * D + lane * 4;
        asm volatile("red.global.add.v4.f32 [%0], {%1,%2,%3,%4};"
                     :: "l"(pp), "f"(acc.x), "f"(acc.y), "f"(acc.z), "f"(acc.w)
                     : "memory");
    }
}

// ---------------------------------------------------------------------------
// head: pooled mean -> linear(128->10) -> log_softmax. One warp per graph.
// ---------------------------------------------------------------------------
__global__ void k_head(const float* __restrict__ Wf, const float* __restrict__ bf,
                       float* __restrict__ out) {
    int g = blockIdx.x;
    int lane = threadIdx.x;
    float inv = 1.0f / fmaxf(g_pcnt[g], 1.0f);
    float logit = -INFINITY;
    if (lane < O) {
        float s = bf[lane];
        const float* pr = g_pool + (size_t)g * D;
#pragma unroll 8
        for (int k = 0; k < D; k++)
            s += pr[k] * inv * Wf[k * O + lane];
        logit = s;
    }
    float m = logit;
#pragma unroll
    for (int o = 16; o; o >>= 1) m = fmaxf(m, __shfl_xor_sync(0xffffffffu, m, o));
    float e = (lane < O) ? expf(logit - m) : 0.0f;
    float se = e;
#pragma unroll
    for (int o = 16; o; o >>= 1) se += __shfl_xor_sync(0xffffffffu, se, o);
    if (lane < O) out[g * O + lane] = logit - m - logf(se);
}

// ---------------------------------------------------------------------------
extern "C" void kernel_launch(void* const* d_in, const int* in_sizes, int n_in,
                              void* d_out, int out_size) {
    const float* x     = (const float*)d_in[0];
    const int*   ei    = (const int*)d_in[1];
    const int*   batch = (const int*)d_in[2];
    const float* W0 = (const float*)d_in[3];
    const float* b0 = (const float*)d_in[4];
    const float* W1 = (const float*)d_in[5];
    const float* b1 = (const float*)d_in[6];
    const float* W2 = (const float*)d_in[7];
    const float* b2 = (const float*)d_in[8];
    const float* Wf = (const float*)d_in[9];
    const float* bf = (const float*)d_in[10];
    float* out = (float*)d_out;

    cudaFuncSetAttribute(k_gemm_tc, cudaFuncAttributeMaxDynamicSharedMemorySize,
                         SMEM_GEMM_BYTES);

    // Side stream + events for fork/join inside the captured graph.
    static cudaStream_t s2 = nullptr;
    static cudaEvent_t e_fork = nullptr, e_join = nullptr;
    if (!s2) {
        cudaStreamCreateWithFlags(&s2, cudaStreamNonBlocking);
        cudaEventCreateWithFlags(&e_fork, cudaEventDisableTiming);
        cudaEventCreateWithFlags(&e_join, cudaEventDisableTiming);
    }

    // Fork: CSR build chain on s2, concurrent with layer-0 GEMM on main stream.
    cudaEventRecord(e_fork, 0);
    cudaStreamWaitEvent(s2, e_fork, 0);

    k_prep<<<(G * D + 255) / 256, 256, 0, s2>>>();
    k_count<<<(N_EDGES + 255) / 256, 256, 0, s2>>>(ei);
    k_scan1<<<NBLK, 256, 0, s2>>>();
    k_scan2<<<1, 256, 0, s2>>>();
    k_scan3<<<NBLK, 256, 0, s2>>>();
    k_fill<<<(N_EDGES + 255) / 256, 256, 0, s2>>>(ei);
    cudaEventRecord(e_join, s2);

    // Layer-0 GEMM depends only on x/W0 — concurrent with CSR build.
    k_gemm_tc<<<GEMM_TILES, 256, SMEM_GEMM_BYTES>>>(x, W0, 1, N_NODES);
    // pcnt needs only batch; feeds only k_head.
    k_pcnt<<<(G + 255) / 256, 256>>>(batch);

    // Join: everything after needs the CSR.
    cudaStreamWaitEvent(0, e_join, 0);

    const float* Ws[3] = {W0, W1, W2};
    const float* bs[3] = {b0, b1, b2};
    int agg_blocks = (N_NODES * 32 + 255) / 256;

    for (int l = 0; l < 3; l++) {
        if (l > 0)
            k_gemm_tc<<<GEMM_TILES, 256, SMEM_GEMM_BYTES>>>(x, Ws[l], 0, N_NODES);
        k_agg<<<agg_blocks, 256>>>(bs[l], batch, l == 2 ? 1 : 0);
    }

    k_head<<<G, 32>>>(Wf, bf, out);
}

// round 17
// speedup vs baseline: 1.5216x; 1.2940x over previous
#include <cuda_runtime.h>
#include <cuda_bf16.h>
#include <cuda_fp16.h>
#include <math.h>
#include <stdint.h>

#define N_NODES 50000
#define N_EDGES 600000
#define D 128
#define G 512
#define O 10
#define NBLK 196               // ceil(50000/256)
#define GEMM_TILES 391         // ceil(50000/128)

// Scratch (allocation-free rule: __device__ globals)
__device__ __align__(128) __half g_Ah[N_NODES * D]; // hW buffer (fp16 — gather)
__device__ __align__(128) float g_B[N_NODES * D];   // h buffer (fp32 — GEMM in)
__device__ __align__(128) float g_dis[N_NODES];
__device__ __align__(128) int   g_cnt[N_NODES];
__device__ __align__(128) int   g_rowptr[N_NODES];
__device__ __align__(128) int   g_cursor[N_NODES];
__device__ __align__(128) int   g_csrc[N_EDGES];
__device__ __align__(128) float g_cnrm[N_EDGES];
__device__ __align__(128) int   g_bsum[NBLK];
__device__ __align__(128) int   g_boff[NBLK];
__device__ __align__(128) float g_pool[G * D];
__device__ __align__(128) float g_pcnt[G];

// ---------------------------------------------------------------------------
// prep: zero cnt + pool
// ---------------------------------------------------------------------------
__global__ void k_prep() {
    int i = blockIdx.x * blockDim.x + threadIdx.x;
    if (i < N_NODES) g_cnt[i] = 0;
    if (i < G * D)   g_pool[i] = 0.0f;
}

__global__ void k_count(const int* __restrict__ ei) {
    int e = blockIdx.x * blockDim.x + threadIdx.x;
    if (e < N_EDGES) atomicAdd(&g_cnt[ei[N_EDGES + e]], 1);
}

// 3-phase exclusive scan of g_cnt -> g_rowptr ; also compute dis
__global__ void k_scan1() {
    __shared__ int s[256];
    int t = threadIdx.x;
    int i = blockIdx.x * 256 + t;
    int v = (i < N_NODES) ? g_cnt[i] : 0;
    if (i < N_NODES) g_dis[i] = rsqrtf((float)v + 1.0f);
    s[t] = v;
#pragma unroll
    for (int off = 1; off < 256; off <<= 1) {
        __syncthreads();
        int tmp = (t >= off) ? s[t - off] : 0;
        __syncthreads();
        s[t] += tmp;
    }
    if (i < N_NODES) g_rowptr[i] = s[t] - v;
    if (t == 255) g_bsum[blockIdx.x] = s[255];
}

__global__ void k_scan2() {
    __shared__ int s[256];
    int t = threadIdx.x;
    int v = (t < NBLK) ? g_bsum[t] : 0;
    s[t] = v;
#pragma unroll
    for (int off = 1; off < 256; off <<= 1) {
        __syncthreads();
        int tmp = (t >= off) ? s[t - off] : 0;
        __syncthreads();
        s[t] += tmp;
    }
    if (t < NBLK) g_boff[t] = s[t] - v;
}

__global__ void k_scan3() {
    int i = blockIdx.x * 256 + threadIdx.x;
    if (i < N_NODES) {
        int r = g_rowptr[i] + g_boff[blockIdx.x];
        g_rowptr[i] = r;
        g_cursor[i] = r;
    }
}

__global__ void k_fill(const int* __restrict__ ei) {
    int e = blockIdx.x * blockDim.x + threadIdx.x;
    if (e >= N_EDGES) return;
    int s = ei[e];
    int d = ei[N_EDGES + e];
    int pos = atomicAdd(&g_cursor[d], 1);
    g_csrc[pos] = s;
    g_cnrm[pos] = g_dis[s] * g_dis[d];
}

__global__ void k_pcnt(const int* __restrict__ batch) {
    int g = blockIdx.x * blockDim.x + threadIdx.x;
    if (g >= G) return;
    int lo = 0, hi = N_NODES;
    while (lo < hi) { int m = (lo + hi) >> 1; if (batch[m] < g) lo = m + 1; else hi = m; }
    int lb = lo;
    lo = 0; hi = N_NODES;
    while (lo < hi) { int m = (lo + hi) >> 1; if (batch[m] <= g) lo = m + 1; else hi = m; }
    g_pcnt[g] = (float)(lo - lb);
}

// ---------------------------------------------------------------------------
__device__ __forceinline__ uint32_t f2tf32(float v) {
    uint32_t h;
    asm("cvt.rna.tf32.f32 %0, %1;" : "=r"(h) : "f"(v));
    return h;
}

__device__ __forceinline__ void mma_tf32(float* c, const uint32_t* a, const uint32_t* b) {
    asm volatile(
        "mma.sync.aligned.m16n8k8.row.col.f32.tf32.tf32.f32 "
        "{%0,%1,%2,%3}, {%4,%5,%6,%7}, {%8,%9}, {%0,%1,%2,%3};"
        : "+f"(c[0]), "+f"(c[1]), "+f"(c[2]), "+f"(c[3])
        : "r"(a[0]), "r"(a[1]), "r"(a[2]), "r"(a[3]), "r"(b[0]), "r"(b[1]));
}

// ---------------------------------------------------------------------------
// GEMM via mma.sync tf32 (single-pass — measured 2000x noise attenuation
// makes the lo-correction unnecessary): g_Ah = fp16(in @ W)
// BM=128, BN=128, BK=32 x 4 phases. 256 threads = 8 warps (2m x 4n),
// warp tile 64x32. Structure byte-identical to the proven kernel minus
// the lo half (smem 35.8KB, same launch bounds).
// ---------------------------------------------------------------------------
#define A_STRIDE 36
#define B_STRIDE 136
#define SM_AHI 0
#define SM_BHI (128 * A_STRIDE)
#define SMEM_GEMM_FLOATS (128 * A_STRIDE + 32 * B_STRIDE)
#define SMEM_GEMM_BYTES (SMEM_GEMM_FLOATS * 4)

__global__ void __launch_bounds__(256, 2) k_gemm_tc(const float* __restrict__ Xin,
                                                    const float* __restrict__ W,
                                                    int use_x, int n) {
    extern __shared__ float sm[];
    const float* A = use_x ? Xin : (const float*)g_B;

    int tid = threadIdx.x;
    int wid = tid >> 5, lane = tid & 31;
    int warp_m = wid >> 2, warp_n = wid & 3;
    int lg = lane >> 2, lt = lane & 3;     // groupID, threadID_in_group
    int row0 = blockIdx.x * 128;

    float acc[4][4][4];
#pragma unroll
    for (int mt = 0; mt < 4; mt++)
#pragma unroll
        for (int nt = 0; nt < 4; nt++)
#pragma unroll
            for (int q = 0; q < 4; q++) acc[mt][nt][q] = 0.0f;

    for (int p = 0; p < 4; p++) {
        int k0 = p * 32;
        // stage A chunk: 128 rows x 32 cols = 1024 float4s, 4 per thread
#pragma unroll
        for (int i = 0; i < 4; i++) {
            int idx = tid + i * 256;
            int row = idx >> 3, cq = idx & 7;
            int gr = row0 + row;
            float4 v = make_float4(0.f, 0.f, 0.f, 0.f);
            if (gr < n) v = *(const float4*)(A + (size_t)gr * D + k0 + cq * 4);
            *(uint4*)&sm[SM_AHI + row * A_STRIDE + cq * 4] =
                make_uint4(f2tf32(v.x), f2tf32(v.y), f2tf32(v.z), f2tf32(v.w));
        }
        // stage B chunk: 32 k-rows x 128 cols = 1024 float4s, 4 per thread
#pragma unroll
        for (int i = 0; i < 4; i++) {
            int idx = tid + i * 256;
            int kk = idx >> 5, nq = idx & 31;
            float4 v = *(const float4*)(W + (size_t)(k0 + kk) * D + nq * 4);
            *(uint4*)&sm[SM_BHI + kk * B_STRIDE + nq * 4] =
                make_uint4(f2tf32(v.x), f2tf32(v.y), f2tf32(v.z), f2tf32(v.w));
        }
        __syncthreads();

#pragma unroll
        for (int kk = 0; kk < 4; kk++) {
            int kb = kk * 8;
            uint32_t bhi[4][2];
#pragma unroll
            for (int nt = 0; nt < 4; nt++) {
                int col = warp_n * 32 + nt * 8 + lg;
                bhi[nt][0] = __float_as_uint(sm[SM_BHI + (kb + lt) * B_STRIDE + col]);
                bhi[nt][1] = __float_as_uint(sm[SM_BHI + (kb + lt + 4) * B_STRIDE + col]);
            }
#pragma unroll
            for (int mt = 0; mt < 4; mt++) {
                int rbase = warp_m * 64 + mt * 16;
                uint32_t ahi[4];
                ahi[0] = __float_as_uint(sm[SM_AHI + (rbase + lg) * A_STRIDE + kb + lt]);
                ahi[1] = __float_as_uint(sm[SM_AHI + (rbase + lg + 8) * A_STRIDE + kb + lt]);
                ahi[2] = __float_as_uint(sm[SM_AHI + (rbase + lg) * A_STRIDE + kb + lt + 4]);
                ahi[3] = __float_as_uint(sm[SM_AHI + (rbase + lg + 8) * A_STRIDE + kb + lt + 4]);
#pragma unroll
                for (int nt = 0; nt < 4; nt++)
                    mma_tf32(acc[mt][nt], ahi, bhi[nt]);
            }
        }
        __syncthreads();
    }

    // epilogue: write fp16 to g_Ah
#pragma unroll
    for (int mt = 0; mt < 4; mt++) {
        int r0 = row0 + warp_m * 64 + mt * 16 + lg;
#pragma unroll
        for (int nt = 0; nt < 4; nt++) {
            int col = warp_n * 32 + nt * 8 + 2 * lt;
            if (r0 < n)
                *(__half2*)(g_Ah + (size_t)r0 * D + col) =
                    __floats2half2_rn(acc[mt][nt][0], acc[mt][nt][1]);
            if (r0 + 8 < n)
                *(__half2*)(g_Ah + (size_t)(r0 + 8) * D + col) =
                    __floats2half2_rn(acc[mt][nt][2], acc[mt][nt][3]);
        }
    }
}

// ---------------------------------------------------------------------------
// fused aggregate: warp per node; gathers fp16 rows, accumulates fp32.
// ---------------------------------------------------------------------------
__global__ void k_agg(const float* __restrict__ bias,
                      const int* __restrict__ batch, int doPool) {
    int gt = blockIdx.x * blockDim.x + threadIdx.x;
    int w = gt >> 5;
    if (w >= N_NODES) return;
    int lane = gt & 31;

    float dv = g_dis[w];
    float sn = dv * dv;

    uint2 rh = *(const uint2*)(g_Ah + (size_t)w * D + lane * 4);
    float2 h01 = __half22float2(*(const __half2*)&rh.x);
    float2 h23 = __half22float2(*(const __half2*)&rh.y);
    float4 acc = make_float4(sn * h01.x, sn * h01.y, sn * h23.x, sn * h23.y);

    int beg = g_rowptr[w];
    int end = beg + g_cnt[w];
    for (int k = beg; k < end; k++) {
        int s = g_csrc[k];
        float nr = g_cnrm[k];
        uint2 rv = *(const uint2*)(g_Ah + (size_t)s * D + lane * 4);
        float2 v01 = __half22float2(*(const __half2*)&rv.x);
        float2 v23 = __half22float2(*(const __half2*)&rv.y);
        acc.x += nr * v01.x; acc.y += nr * v01.y;
        acc.z += nr * v23.x; acc.w += nr * v23.y;
    }

    float4 bb = ((const float4*)bias)[lane];
    acc.x = fmaxf(acc.x + bb.x, 0.f);
    acc.y = fmaxf(acc.y + bb.y, 0.f);
    acc.z = fmaxf(acc.z + bb.z, 0.f);
    acc.w = fmaxf(acc.w + bb.w, 0.f);
    ((float4*)(g_B + (size_t)w * D))[lane] = acc;

    if (doPool) {
        float* pp = g_pool + (size_t)batch[w] * D + lane * 4;
        asm volatile("red.global.add.v4.f32 [%0], {%1,%2,%3,%4};"
                     :: "l"(pp), "f"(acc.x), "f"(acc.y), "f"(acc.z), "f"(acc.w)
                     : "memory");
    }
}

// ---------------------------------------------------------------------------
// head: pooled mean -> linear(128->10) -> log_softmax. One warp per graph.
// ---------------------------------------------------------------------------
__global__ void k_head(const float* __restrict__ Wf, const float* __restrict__ bf,
                       float* __restrict__ out) {
    int g = blockIdx.x;
    int lane = threadIdx.x;
    float inv = 1.0f / fmaxf(g_pcnt[g], 1.0f);
    float logit = -INFINITY;
    if (lane < O) {
        float s = bf[lane];
        const float* pr = g_pool + (size_t)g * D;
#pragma unroll 8
        for (int k = 0; k < D; k++)
            s += pr[k] * inv * Wf[k * O + lane];
        logit = s;
    }
    float m = logit;
#pragma unroll
    for (int o = 16; o; o >>= 1) m = fmaxf(m, __shfl_xor_sync(0xffffffffu, m, o));
    float e = (lane < O) ? expf(logit - m) : 0.0f;
    float se = e;
#pragma unroll
    for (int o = 16; o; o >>= 1) se += __shfl_xor_sync(0xffffffffu, se, o);
    if (lane < O) out[g * O + lane] = logit - m - logf(se);
}

// ---------------------------------------------------------------------------
extern "C" void kernel_launch(void* const* d_in, const int* in_sizes, int n_in,
                              void* d_out, int out_size) {
    const float* x     = (const float*)d_in[0];
    const int*   ei    = (const int*)d_in[1];
    const int*   batch = (const int*)d_in[2];
    const float* W0 = (const float*)d_in[3];
    const float* b0 = (const float*)d_in[4];
    const float* W1 = (const float*)d_in[5];
    const float* b1 = (const float*)d_in[6];
    const float* W2 = (const float*)d_in[7];
    const float* b2 = (const float*)d_in[8];
    const float* Wf = (const float*)d_in[9];
    const float* bf = (const float*)d_in[10];
    float* out = (float*)d_out;

    cudaFuncSetAttribute(k_gemm_tc, cudaFuncAttributeMaxDynamicSharedMemorySize,
                         SMEM_GEMM_BYTES);

    // Side stream + events for fork/join inside the captured graph.
    static cudaStream_t s2 = nullptr;
    static cudaEvent_t e_fork = nullptr, e_join = nullptr;
    if (!s2) {
        cudaStreamCreateWithFlags(&s2, cudaStreamNonBlocking);
        cudaEventCreateWithFlags(&e_fork, cudaEventDisableTiming);
        cudaEventCreateWithFlags(&e_join, cudaEventDisableTiming);
    }

    // Fork: CSR build chain on s2, concurrent with layer-0 GEMM on main stream.
    cudaEventRecord(e_fork, 0);
    cudaStreamWaitEvent(s2, e_fork, 0);

    k_prep<<<(G * D + 255) / 256, 256, 0, s2>>>();
    k_count<<<(N_EDGES + 255) / 256, 256, 0, s2>>>(ei);
    k_scan1<<<NBLK, 256, 0, s2>>>();
    k_scan2<<<1, 256, 0, s2>>>();
    k_scan3<<<NBLK, 256, 0, s2>>>();
    k_fill<<<(N_EDGES + 255) / 256, 256, 0, s2>>>(ei);
    cudaEventRecord(e_join, s2);

    // Layer-0 GEMM depends only on x/W0 — concurrent with CSR build.
    k_gemm_tc<<<GEMM_TILES, 256, SMEM_GEMM_BYTES>>>(x, W0, 1, N_NODES);
    // pcnt needs only batch; feeds only k_head.
    k_pcnt<<<(G + 255) / 256, 256>>>(batch);

    // Join: everything after needs the CSR.
    cudaStreamWaitEvent(0, e_join, 0);

    const float* Ws[3] = {W0, W1, W2};
    const float* bs[3] = {b0, b1, b2};
    int agg_blocks = (N_NODES * 32 + 255) / 256;

    for (int l = 0; l < 3; l++) {
        if (l > 0)
            k_gemm_tc<<<GEMM_TILES, 256, SMEM_GEMM_BYTES>>>(x, Ws[l], 0, N_NODES);
        k_agg<<<agg_blocks, 256>>>(bs[l], batch, l == 2 ? 1 : 0);
    }

    k_head<<<G, 32>>>(Wf, bf, out);
}